// round 13
// baseline (speedup 1.0000x reference)
#include <cuda_runtime.h>
#include <cuda_fp16.h>
#include <stdint.h>

// Problem constants
#define B_   4
#define L_   2048
#define D_   1024
#define H_   16
#define HD_  64
#define NTOK (B_ * L_)   // 8192

// ---------------------------------------------------------------------------
// Scratch (__device__ globals; allocations are banned)
// ---------------------------------------------------------------------------
__device__ __half g_qkv_h[(size_t)NTOK * 3 * D_];   // [B,L,3D] fp16
__device__ __half g_x_h[(size_t)NTOK * D_];         // x as plain fp16
__device__ __half g_y_h[(size_t)NTOK * D_];         // y as plain fp16
__device__ __half g_wqkv_h[(size_t)3 * D_ * D_];    // [3072][1024] (W^T) fp16
__device__ __half g_wproj_h[(size_t)D_ * D_];       // [1024][1024] (W^T) fp16

// ---------------------------------------------------------------------------
// Helpers (baseline sm_80-class ISA: ldmatrix / mma.sync / cp.async)
// ---------------------------------------------------------------------------
__device__ __forceinline__ uint32_t smem_u32(const void* p) {
    uint32_t a;
    asm("{ .reg .u64 t; cvta.to.shared.u64 t, %1; cvt.u32.u64 %0, t; }"
        : "=r"(a) : "l"(p));
    return a;
}
__device__ __forceinline__ void ldm_x4(uint32_t& r0, uint32_t& r1,
                                       uint32_t& r2, uint32_t& r3, uint32_t addr) {
    asm volatile("ldmatrix.sync.aligned.m8n8.x4.shared.b16 {%0,%1,%2,%3}, [%4];"
                 : "=r"(r0), "=r"(r1), "=r"(r2), "=r"(r3) : "r"(addr));
}
__device__ __forceinline__ void ldm_x4_t(uint32_t& r0, uint32_t& r1,
                                         uint32_t& r2, uint32_t& r3, uint32_t addr) {
    asm volatile("ldmatrix.sync.aligned.m8n8.x4.trans.shared.b16 {%0,%1,%2,%3}, [%4];"
                 : "=r"(r0), "=r"(r1), "=r"(r2), "=r"(r3) : "r"(addr));
}
__device__ __forceinline__ void mma_f16(float* c, const uint32_t* a,
                                        const uint32_t* b) {
    asm volatile(
        "mma.sync.aligned.m16n8k16.row.col.f32.f16.f16.f32 "
        "{%0,%1,%2,%3}, {%4,%5,%6,%7}, {%8,%9}, {%0,%1,%2,%3};"
        : "+f"(c[0]), "+f"(c[1]), "+f"(c[2]), "+f"(c[3])
        : "r"(a[0]), "r"(a[1]), "r"(a[2]), "r"(a[3]), "r"(b[0]), "r"(b[1]));
}
__device__ __forceinline__ void cp_async16(uint32_t saddr, const void* gptr) {
    asm volatile("cp.async.cg.shared.global [%0], [%1], 16;"
                 :: "r"(saddr), "l"(gptr));
}
__device__ __forceinline__ void cp_commit() {
    asm volatile("cp.async.commit_group;" ::: "memory");
}
template <int N>
__device__ __forceinline__ void cp_wait() {
    asm volatile("cp.async.wait_group %0;" :: "n"(N) : "memory");
}
// pack two fp32 -> half2 (first arg in low half, second in high half)
__device__ __forceinline__ uint32_t pack_h2(float lo, float hi) {
    __half2 t = __floats2half2_rn(lo, hi);
    return *(uint32_t*)&t;
}

// Swizzles: 64B rows (gemm) and 128B rows (attention)
__device__ __forceinline__ uint32_t sw64(uint32_t off) {
    return off ^ (((off >> 7) & 3u) << 4);
}
__device__ __forceinline__ uint32_t sw128(uint32_t off) {
    return off ^ ((off >> 3) & 0x70u);
}

// ---------------------------------------------------------------------------
// Convert fp32 -> plain fp16 (vectorized)
// ---------------------------------------------------------------------------
__global__ __launch_bounds__(256) void convert_kernel(
    const float* __restrict__ X, __half* __restrict__ Hp, int n4)
{
    int i = blockIdx.x * blockDim.x + threadIdx.x;
    if (i >= n4) return;
    float4 v = ((const float4*)X)[i];
    uint2 o;
    o.x = pack_h2(v.x, v.y);
    o.y = pack_h2(v.z, v.w);
    *(uint2*)(Hp + (size_t)i * 4) = o;
}

// ---------------------------------------------------------------------------
// Transpose + convert: W[K][N] fp32 -> T[N][K] fp16
// ---------------------------------------------------------------------------
__global__ __launch_bounds__(256) void transpose_convert_kernel(
    const float* __restrict__ W, __half* __restrict__ Th, int K, int N)
{
    __shared__ float tile[32][33];
    int n0 = blockIdx.x * 32;
    int k0 = blockIdx.y * 32;
    int tx = threadIdx.x, ty = threadIdx.y;   // block 32x8
#pragma unroll
    for (int j = 0; j < 4; j++) {
        tile[ty + j * 8][tx] = W[(size_t)(k0 + ty + j * 8) * N + n0 + tx];
    }
    __syncthreads();
#pragma unroll
    for (int j = 0; j < 4; j++) {
        float v = tile[tx][ty + j * 8];       // = W[k0+tx][n0+ty+j*8]
        Th[(size_t)(n0 + ty + j * 8) * K + k0 + tx] = __float2half_rn(v);
    }
}

// ---------------------------------------------------------------------------
// HMMA plain-fp16 GEMM: C = A @ W, A [M,K] fp16, W^T [N,K] fp16.
// 128x128 CTA tile, 256 thr, 8 warps of 64x32 tiles, BK=32, 4-stage ring,
// 64KB smem, 2 CTAs/SM. Epilogue: fp32 C (Ch==null) or plain fp16 (Ch).
// ---------------------------------------------------------------------------
#define CT_BK 32
#define BUF_B 8192
#define G_STAGE_B (2 * BUF_B)          // A, B = 16384
#define G_NSTAGE 4
#define GEMM_SMEM (G_NSTAGE * G_STAGE_B)   // 65536

__device__ __forceinline__ void issue_stage(
    const __half* __restrict__ A, const __half* __restrict__ Bh,
    int K, int row_a0, int row_b0, int k0,
    uint32_t sb, int stage, int tid)
{
    uint32_t base = sb + stage * G_STAGE_B;
#pragma unroll
    for (int j = 0; j < 2; j++) {
        int idx = tid + j * 256;          // 0..511
        int r = idx >> 2;                 // 0..127
        int ch = idx & 3;                 // 16B chunk
        uint32_t so = sw64((uint32_t)(r * 64 + ch * 16));
        cp_async16(base + 0 * BUF_B + so,
                   A + (size_t)(row_a0 + r) * K + k0 + ch * 8);
        cp_async16(base + 1 * BUF_B + so,
                   Bh + (size_t)(row_b0 + r) * K + k0 + ch * 8);
    }
}

__global__ __launch_bounds__(256, 2) void gemm_mma_kernel(
    const __half* __restrict__ A, const __half* __restrict__ Bh,
    float* __restrict__ C, __half* __restrict__ Ch, int M, int N, int K)
{
    extern __shared__ char smem[];
    uint32_t sb = smem_u32(smem);
    const int tid = threadIdx.x;
    const int wid = tid >> 5;
    const int lane = tid & 31;
    const int warp_m = wid >> 2;
    const int warp_n = wid & 3;

    const int row_a0 = blockIdx.y * 128;
    const int row_b0 = blockIdx.x * 128;
    const int niter = K / CT_BK;       // 32

    float acc[4][4][4];
#pragma unroll
    for (int i = 0; i < 4; i++)
#pragma unroll
        for (int j = 0; j < 4; j++)
#pragma unroll
            for (int t = 0; t < 4; t++) acc[i][j][t] = 0.0f;

    const int lr = lane & 7;
    const int mat = lane >> 3;
    const int a_radd = lr + (mat & 1) * 8;
    const int a_cadd = (mat >> 1) * 16;
    const int b_radd = lr + (mat >> 1) * 8;
    const int b_cadd = (mat & 1) * 16;

    // Prologue: 3 stages in flight
    issue_stage(A, Bh, K, row_a0, row_b0, 0 * CT_BK, sb, 0, tid); cp_commit();
    issue_stage(A, Bh, K, row_a0, row_b0, 1 * CT_BK, sb, 1, tid); cp_commit();
    issue_stage(A, Bh, K, row_a0, row_b0, 2 * CT_BK, sb, 2, tid); cp_commit();

    int stage = 0;
    for (int i = 0; i < niter; i++) {
        if (i < niter - 2) cp_wait<2>();
        else if (i == niter - 2) cp_wait<1>();
        else cp_wait<0>();
        __syncthreads();
        if (i + 3 < niter) {
            int ws = stage + 3; if (ws >= G_NSTAGE) ws -= G_NSTAGE;
            issue_stage(A, Bh, K, row_a0, row_b0, (i + 3) * CT_BK, sb, ws, tid);
            cp_commit();
        }

        const uint32_t stg = sb + stage * G_STAGE_B;
#pragma unroll
        for (int ks = 0; ks < 2; ks++) {
            const int kb0 = ks * 32;
            uint32_t ah[4][4];
#pragma unroll
            for (int mt = 0; mt < 4; mt++) {
                uint32_t roff = (uint32_t)((warp_m * 64 + mt * 16 + a_radd) * 64
                                           + kb0 + a_cadd);
                ldm_x4(ah[mt][0], ah[mt][1], ah[mt][2], ah[mt][3],
                       stg + 0 * BUF_B + sw64(roff));
            }
#pragma unroll
            for (int bp = 0; bp < 2; bp++) {
                uint32_t roff = (uint32_t)((warp_n * 32 + bp * 16 + b_radd) * 64
                                           + kb0 + b_cadd);
                uint32_t h[4];
                ldm_x4(h[0], h[1], h[2], h[3], stg + 1 * BUF_B + sw64(roff));
#pragma unroll
                for (int mt = 0; mt < 4; mt++) {
                    mma_f16(acc[mt][2 * bp + 0], ah[mt], &h[0]);
                    mma_f16(acc[mt][2 * bp + 1], ah[mt], &h[2]);
                }
            }
        }
        stage++; if (stage >= G_NSTAGE) stage = 0;
    }

    const int qr = lane >> 2;
    const int qc = (lane & 3) * 2;
#pragma unroll
    for (int mt = 0; mt < 4; mt++) {
        int row = row_a0 + warp_m * 64 + mt * 16 + qr;
#pragma unroll
        for (int nt = 0; nt < 4; nt++) {
            int col = row_b0 + warp_n * 32 + nt * 8 + qc;
            if (Ch == nullptr) {
                *(float2*)(C + (size_t)row * N + col) =
                    make_float2(acc[mt][nt][0], acc[mt][nt][1]);
                *(float2*)(C + (size_t)(row + 8) * N + col) =
                    make_float2(acc[mt][nt][2], acc[mt][nt][3]);
            } else {
                *(uint32_t*)(Ch + (size_t)row * N + col) =
                    pack_h2(acc[mt][nt][0], acc[mt][nt][1]);
                *(uint32_t*)(Ch + (size_t)(row + 8) * N + col) =
                    pack_h2(acc[mt][nt][2], acc[mt][nt][3]);
            }
        }
    }
}

// ---------------------------------------------------------------------------
// HMMA fp16 flash attention (causal), plain fp16 Q/K/V/P (unchanged from R11).
// 128 q-rows/CTA, 64-kv tiles, 8 warps x 16 rows.
// Smem: Q 16KB + 2 stages x {K 8KB, V 8KB} = 48KB. 2 CTAs/SM.
// ---------------------------------------------------------------------------
#define SM_Q 0
#define SM_KV0 16384
#define AT_STAGE_B 16384
#define AT_SMEM 49152

__device__ __forceinline__ void at_issue_kv(
    const __half* __restrict__ qkvh,
    size_t qoff, size_t rs, int kv0, uint32_t sb, int stage, int tid)
{
    uint32_t base = sb + SM_KV0 + stage * AT_STAGE_B;
#pragma unroll
    for (int t = 0; t < 2; t++) {
        int idx = tid + t * 256;
        int r = idx >> 3;
        int ch = idx & 7;
        uint32_t so = sw128((uint32_t)(r * 128 + ch * 16));
        size_t gk = qoff + D_ + (size_t)(kv0 + r) * rs + ch * 8;
        size_t gv = qoff + 2 * D_ + (size_t)(kv0 + r) * rs + ch * 8;
        cp_async16(base + 0 * 8192 + so, qkvh + gk);
        cp_async16(base + 1 * 8192 + so, qkvh + gv);
    }
}

__global__ __launch_bounds__(256, 2) void attn_mma_kernel(
    const __half* __restrict__ qkvh, __half* __restrict__ yh)
{
    extern __shared__ char smc[];
    uint32_t sb = smem_u32(smc);
    const int tid = threadIdx.x;
    const int wid = tid >> 5;
    const int lane = tid & 31;
    const int b = blockIdx.z;
    const int h = blockIdx.y;
    const int qt = gridDim.x - 1 - blockIdx.x;   // long CTAs first
    const int q0 = qt * 128;
    const int wm = wid * 16;
    const int nkv = 2 * qt + 2;

    const size_t rs = 3 * D_;
    const size_t qoff = (size_t)(b * L_) * rs + h * HD_;

    // Prologue: Q + KV stage 0 in one cp.async group
#pragma unroll
    for (int t = 0; t < 4; t++) {
        int idx = tid + t * 256;
        int r = idx >> 3;
        int ch = idx & 7;
        uint32_t so = sw128((uint32_t)(r * 128 + ch * 16));
        size_t g = qoff + (size_t)(q0 + r) * rs + ch * 8;
        cp_async16(sb + SM_Q + so, qkvh + g);
    }
    at_issue_kv(qkvh, qoff, rs, 0, sb, 0, tid);
    cp_commit();

    // ldmatrix lane address components
    const int lr = lane & 7;
    const int mat = lane >> 3;
    const int a_radd = lr + (mat & 1) * 8;       // A (non-trans)
    const int a_cadd = (mat >> 1) * 16;
    const int b_radd = lr + (mat >> 1) * 8;      // B (non-trans, K)
    const int b_cadd = (mat & 1) * 16;
    const int v_radd = lr + (mat & 1) * 8;       // B (trans, V)
    const int v_cadd = (mat >> 1) * 16;
    const int qr = lane >> 2;
    const int qc2 = (lane & 3) * 2;

    float m2[2] = {-1e30f, -1e30f};
    float l2[2] = {0.0f, 0.0f};
    float o[8][4];
#pragma unroll
    for (int ng = 0; ng < 8; ng++)
#pragma unroll
        for (int e = 0; e < 4; e++) o[ng][e] = 0.0f;

    for (int jt = 0; jt < nkv; jt++) {
        cp_wait<0>();      // group jt complete
        __syncthreads();   // all warps done reading stage (jt-1)&1
        if (jt + 1 < nkv) {
            at_issue_kv(qkvh, qoff, rs, (jt + 1) * 64, sb, (jt + 1) & 1, tid);
            cp_commit();
        }

        const uint32_t kb = sb + SM_KV0 + (jt & 1) * AT_STAGE_B;

        // ---- S = Q @ K^T ----
        float s[8][4];
#pragma unroll
        for (int ng = 0; ng < 8; ng++)
#pragma unroll
            for (int e = 0; e < 4; e++) s[ng][e] = 0.0f;

#pragma unroll
        for (int k = 0; k < 4; k++) {
            uint32_t ah[4];
            uint32_t aoff = sw128((uint32_t)((wm + a_radd) * 128 + k * 32 + a_cadd));
            ldm_x4(ah[0], ah[1], ah[2], ah[3], sb + SM_Q + aoff);
#pragma unroll
            for (int bp = 0; bp < 4; bp++) {
                uint32_t roff = sw128((uint32_t)((bp * 16 + b_radd) * 128
                                                 + k * 32 + b_cadd));
                uint32_t bh[4];
                ldm_x4(bh[0], bh[1], bh[2], bh[3], kb + 0 * 8192 + roff);
                mma_f16(s[2 * bp + 0], ah, &bh[0]);
                mma_f16(s[2 * bp + 1], ah, &bh[2]);
            }
        }

        // ---- scale + causal mask ----
        const float scale = 0.125f;
        if (jt >= nkv - 2) {
#pragma unroll
            for (int ng = 0; ng < 8; ng++)
#pragma unroll
                for (int e = 0; e < 4; e++) {
                    int rg = q0 + wm + qr + (e >> 1) * 8;
                    int cg = jt * 64 + ng * 8 + qc2 + (e & 1);
                    s[ng][e] = (cg > rg) ? -1e30f : s[ng][e] * scale;
                }
        } else {
#pragma unroll
            for (int ng = 0; ng < 8; ng++)
#pragma unroll
                for (int e = 0; e < 4; e++) s[ng][e] *= scale;
        }

        // ---- online softmax (per-warp; rows qr and qr+8) ----
#pragma unroll
        for (int t = 0; t < 2; t++) {
            float mx = -1e30f;
#pragma unroll
            for (int ng = 0; ng < 8; ng++)
                mx = fmaxf(mx, fmaxf(s[ng][2 * t], s[ng][2 * t + 1]));
            mx = fmaxf(mx, __shfl_xor_sync(0xffffffffu, mx, 1));
            mx = fmaxf(mx, __shfl_xor_sync(0xffffffffu, mx, 2));
            float mnew = fmaxf(m2[t], mx);
            float alpha = __expf(m2[t] - mnew);
            m2[t] = mnew;
            float sum = 0.0f;
#pragma unroll
            for (int ng = 0; ng < 8; ng++) {
                s[ng][2 * t] = __expf(s[ng][2 * t] - mnew);
                s[ng][2 * t + 1] = __expf(s[ng][2 * t + 1] - mnew);
                sum += s[ng][2 * t] + s[ng][2 * t + 1];
            }
            sum += __shfl_xor_sync(0xffffffffu, sum, 1);
            sum += __shfl_xor_sync(0xffffffffu, sum, 2);
            l2[t] = l2[t] * alpha + sum;
#pragma unroll
            for (int ng = 0; ng < 8; ng++) {
                o[ng][2 * t] *= alpha;
                o[ng][2 * t + 1] *= alpha;
            }
        }

        // ---- O += P @ V ----
#pragma unroll
        for (int kk = 0; kk < 4; kk++) {
            uint32_t pah[4];
            pah[0] = pack_h2(s[2 * kk][0], s[2 * kk][1]);
            pah[1] = pack_h2(s[2 * kk][2], s[2 * kk][3]);
            pah[2] = pack_h2(s[2 * kk + 1][0], s[2 * kk + 1][1]);
            pah[3] = pack_h2(s[2 * kk + 1][2], s[2 * kk + 1][3]);
#pragma unroll
            for (int gp = 0; gp < 4; gp++) {
                uint32_t roff = sw128((uint32_t)((kk * 16 + v_radd) * 128
                                                 + gp * 32 + v_cadd));
                uint32_t vh[4];
                ldm_x4_t(vh[0], vh[1], vh[2], vh[3], kb + 1 * 8192 + roff);
                mma_f16(o[2 * gp + 0], pah, &vh[0]);
                mma_f16(o[2 * gp + 1], pah, &vh[2]);
            }
        }
    }

    // ---- normalize + store y as plain fp16 ----
    float inv0 = 1.0f / l2[0];
    float inv1 = 1.0f / l2[1];
    int row0 = b * L_ + q0 + wm + qr;
#pragma unroll
    for (int ng = 0; ng < 8; ng++) {
        int col = h * HD_ + ng * 8 + qc2;
        *(uint32_t*)(yh + (size_t)row0 * D_ + col) =
            pack_h2(o[ng][0] * inv0, o[ng][1] * inv0);
        *(uint32_t*)(yh + (size_t)(row0 + 8) * D_ + col) =
            pack_h2(o[ng][2] * inv1, o[ng][3] * inv1);
    }
}

// ---------------------------------------------------------------------------
// kernel_launch
// ---------------------------------------------------------------------------
extern "C" void kernel_launch(void* const* d_in, const int* in_sizes, int n_in,
                              void* d_out, int out_size)
{
    const float* x     = (const float*)d_in[0];
    const float* Wqkv  = (const float*)d_in[1];
    const float* Wproj = (const float*)d_in[2];
    float* out = (float*)d_out;

    __half *qkvh, *xh, *yh, *wqh, *wph;
    cudaGetSymbolAddress((void**)&qkvh, g_qkv_h);
    cudaGetSymbolAddress((void**)&xh,  g_x_h);
    cudaGetSymbolAddress((void**)&yh,  g_y_h);
    cudaGetSymbolAddress((void**)&wqh, g_wqkv_h);
    cudaGetSymbolAddress((void**)&wph, g_wproj_h);

    cudaFuncSetAttribute(gemm_mma_kernel,
                         cudaFuncAttributeMaxDynamicSharedMemorySize, GEMM_SMEM);
    cudaFuncSetAttribute(attn_mma_kernel,
                         cudaFuncAttributeMaxDynamicSharedMemorySize, AT_SMEM);

    // 1) convert x to fp16 / transpose+convert weights to fp16
    {
        int n4 = NTOK * D_ / 4;
        convert_kernel<<<(n4 + 255) / 256, 256>>>(x, xh, n4);
    }
    transpose_convert_kernel<<<dim3(3 * D_ / 32, D_ / 32), dim3(32, 8)>>>(
        Wqkv, wqh, D_, 3 * D_);
    transpose_convert_kernel<<<dim3(D_ / 32, D_ / 32), dim3(32, 8)>>>(
        Wproj, wph, D_, D_);

    // 2) qkv (plain fp16) = x @ Wqkv
    gemm_mma_kernel<<<dim3(3 * D_ / 128, NTOK / 128), 256, GEMM_SMEM>>>(
        xh, wqh, nullptr, qkvh, NTOK, 3 * D_, D_);

    // 3) flash attention -> y (plain fp16)
    attn_mma_kernel<<<dim3(L_ / 128, H_, B_), 256, AT_SMEM>>>(qkvh, yh);

    // 4) out = y @ Wproj (fp32 output)
    gemm_mma_kernel<<<dim3(D_ / 128, NTOK / 128), 256, GEMM_SMEM>>>(
        yh, wph, out, nullptr, NTOK, D_, D_);
}

// round 16
// speedup vs baseline: 1.4971x; 1.4971x over previous
#include <cuda_runtime.h>
#include <cuda_fp16.h>
#include <stdint.h>

// Problem constants
#define B_   4
#define L_   2048
#define D_   1024
#define H_   16
#define HD_  64
#define NTOK (B_ * L_)   // 8192

// ---------------------------------------------------------------------------
// Scratch (__device__ globals; allocations are banned)
// ---------------------------------------------------------------------------
__device__ __half g_qkv_h[(size_t)NTOK * 3 * D_];   // [B,L,3D] fp16
__device__ __half g_x_h[(size_t)NTOK * D_];         // x as plain fp16
__device__ __half g_y_h[(size_t)NTOK * D_];         // y as plain fp16
__device__ __half g_wqkv_h[(size_t)3 * D_ * D_];    // [3072][1024] (W^T) fp16
__device__ __half g_wproj_h[(size_t)D_ * D_];       // [1024][1024] (W^T) fp16

// ---------------------------------------------------------------------------
// Helpers (baseline sm_80-class ISA: ldmatrix / mma.sync / cp.async)
// ---------------------------------------------------------------------------
__device__ __forceinline__ uint32_t smem_u32(const void* p) {
    uint32_t a;
    asm("{ .reg .u64 t; cvta.to.shared.u64 t, %1; cvt.u32.u64 %0, t; }"
        : "=r"(a) : "l"(p));
    return a;
}
__device__ __forceinline__ void ldm_x4(uint32_t& r0, uint32_t& r1,
                                       uint32_t& r2, uint32_t& r3, uint32_t addr) {
    asm volatile("ldmatrix.sync.aligned.m8n8.x4.shared.b16 {%0,%1,%2,%3}, [%4];"
                 : "=r"(r0), "=r"(r1), "=r"(r2), "=r"(r3) : "r"(addr));
}
__device__ __forceinline__ void ldm_x4_t(uint32_t& r0, uint32_t& r1,
                                         uint32_t& r2, uint32_t& r3, uint32_t addr) {
    asm volatile("ldmatrix.sync.aligned.m8n8.x4.trans.shared.b16 {%0,%1,%2,%3}, [%4];"
                 : "=r"(r0), "=r"(r1), "=r"(r2), "=r"(r3) : "r"(addr));
}
__device__ __forceinline__ void mma_f16(float* c, const uint32_t* a,
                                        const uint32_t* b) {
    asm volatile(
        "mma.sync.aligned.m16n8k16.row.col.f32.f16.f16.f32 "
        "{%0,%1,%2,%3}, {%4,%5,%6,%7}, {%8,%9}, {%0,%1,%2,%3};"
        : "+f"(c[0]), "+f"(c[1]), "+f"(c[2]), "+f"(c[3])
        : "r"(a[0]), "r"(a[1]), "r"(a[2]), "r"(a[3]), "r"(b[0]), "r"(b[1]));
}
__device__ __forceinline__ void cp_async16(uint32_t saddr, const void* gptr) {
    asm volatile("cp.async.cg.shared.global [%0], [%1], 16;"
                 :: "r"(saddr), "l"(gptr));
}
__device__ __forceinline__ void cp_commit() {
    asm volatile("cp.async.commit_group;" ::: "memory");
}
template <int N>
__device__ __forceinline__ void cp_wait() {
    asm volatile("cp.async.wait_group %0;" :: "n"(N) : "memory");
}
// pack two fp32 -> half2 (first arg in low half, second in high half)
__device__ __forceinline__ uint32_t pack_h2(float lo, float hi) {
    __half2 t = __floats2half2_rn(lo, hi);
    return *(uint32_t*)&t;
}

// Swizzles: 64B rows (gemm) and 128B rows (attention)
__device__ __forceinline__ uint32_t sw64(uint32_t off) {
    return off ^ (((off >> 7) & 3u) << 4);
}
__device__ __forceinline__ uint32_t sw128(uint32_t off) {
    return off ^ ((off >> 3) & 0x70u);
}

// ---------------------------------------------------------------------------
// Convert fp32 -> plain fp16 (vectorized)
// ---------------------------------------------------------------------------
__global__ __launch_bounds__(256) void convert_kernel(
    const float* __restrict__ X, __half* __restrict__ Hp, int n4)
{
    int i = blockIdx.x * blockDim.x + threadIdx.x;
    if (i >= n4) return;
    float4 v = ((const float4*)X)[i];
    uint2 o;
    o.x = pack_h2(v.x, v.y);
    o.y = pack_h2(v.z, v.w);
    *(uint2*)(Hp + (size_t)i * 4) = o;
}

// ---------------------------------------------------------------------------
// Transpose + convert: W[K][N] fp32 -> T[N][K] fp16
// ---------------------------------------------------------------------------
__global__ __launch_bounds__(256) void transpose_convert_kernel(
    const float* __restrict__ W, __half* __restrict__ Th, int K, int N)
{
    __shared__ float tile[32][33];
    int n0 = blockIdx.x * 32;
    int k0 = blockIdx.y * 32;
    int tx = threadIdx.x, ty = threadIdx.y;   // block 32x8
#pragma unroll
    for (int j = 0; j < 4; j++) {
        tile[ty + j * 8][tx] = W[(size_t)(k0 + ty + j * 8) * N + n0 + tx];
    }
    __syncthreads();
#pragma unroll
    for (int j = 0; j < 4; j++) {
        float v = tile[tx][ty + j * 8];       // = W[k0+tx][n0+ty+j*8]
        Th[(size_t)(n0 + ty + j * 8) * K + k0 + tx] = __float2half_rn(v);
    }
}

// ---------------------------------------------------------------------------
// HMMA plain-fp16 GEMM: C = A @ W, A [M,K] fp16, W^T [N,K] fp16.
// 128x128 CTA tile, 256 thr, 8 warps of 64x32 tiles, BK=32, 5-stage ring,
// 80KB smem, 2 CTAs/SM. Epilogue: fp32 C (Ch==null) or plain fp16 (Ch).
// ---------------------------------------------------------------------------
#define CT_BK 32
#define BUF_B 8192
#define G_STAGE_B (2 * BUF_B)          // A, B = 16384
#define G_NSTAGE 5
#define GEMM_SMEM (G_NSTAGE * G_STAGE_B)   // 81920

__device__ __forceinline__ void issue_stage(
    const __half* __restrict__ A, const __half* __restrict__ Bh,
    int K, int row_a0, int row_b0, int k0,
    uint32_t sb, int stage, int tid)
{
    uint32_t base = sb + stage * G_STAGE_B;
#pragma unroll
    for (int j = 0; j < 2; j++) {
        int idx = tid + j * 256;          // 0..511
        int r = idx >> 2;                 // 0..127
        int ch = idx & 3;                 // 16B chunk
        uint32_t so = sw64((uint32_t)(r * 64 + ch * 16));
        cp_async16(base + 0 * BUF_B + so,
                   A + (size_t)(row_a0 + r) * K + k0 + ch * 8);
        cp_async16(base + 1 * BUF_B + so,
                   Bh + (size_t)(row_b0 + r) * K + k0 + ch * 8);
    }
}

__global__ __launch_bounds__(256, 2) void gemm_mma_kernel(
    const __half* __restrict__ A, const __half* __restrict__ Bh,
    float* __restrict__ C, __half* __restrict__ Ch, int M, int N, int K)
{
    extern __shared__ char smem[];
    uint32_t sb = smem_u32(smem);
    const int tid = threadIdx.x;
    const int wid = tid >> 5;
    const int lane = tid & 31;
    const int warp_m = wid >> 2;
    const int warp_n = wid & 3;

    const int row_a0 = blockIdx.y * 128;
    const int row_b0 = blockIdx.x * 128;
    const int niter = K / CT_BK;       // 32

    float acc[4][4][4];
#pragma unroll
    for (int i = 0; i < 4; i++)
#pragma unroll
        for (int j = 0; j < 4; j++)
#pragma unroll
            for (int t = 0; t < 4; t++) acc[i][j][t] = 0.0f;

    const int lr = lane & 7;
    const int mat = lane >> 3;
    const int a_radd = lr + (mat & 1) * 8;
    const int a_cadd = (mat >> 1) * 16;
    const int b_radd = lr + (mat >> 1) * 8;
    const int b_cadd = (mat & 1) * 16;

    // Prologue: 4 stages in flight
    issue_stage(A, Bh, K, row_a0, row_b0, 0 * CT_BK, sb, 0, tid); cp_commit();
    issue_stage(A, Bh, K, row_a0, row_b0, 1 * CT_BK, sb, 1, tid); cp_commit();
    issue_stage(A, Bh, K, row_a0, row_b0, 2 * CT_BK, sb, 2, tid); cp_commit();
    issue_stage(A, Bh, K, row_a0, row_b0, 3 * CT_BK, sb, 3, tid); cp_commit();

    int stage = 0;
    for (int i = 0; i < niter; i++) {
        if (i <= niter - 4) cp_wait<3>();
        else if (i == niter - 3) cp_wait<2>();
        else if (i == niter - 2) cp_wait<1>();
        else cp_wait<0>();
        __syncthreads();   // stage i ready; all warps done with its previous use
        if (i + 4 < niter) {
            int ws = stage + 4; if (ws >= G_NSTAGE) ws -= G_NSTAGE;
            issue_stage(A, Bh, K, row_a0, row_b0, (i + 4) * CT_BK, sb, ws, tid);
            cp_commit();
        }

        const uint32_t stg = sb + stage * G_STAGE_B;
#pragma unroll
        for (int ks = 0; ks < 2; ks++) {
            const int kb0 = ks * 32;
            uint32_t ah[4][4];
#pragma unroll
            for (int mt = 0; mt < 4; mt++) {
                uint32_t roff = (uint32_t)((warp_m * 64 + mt * 16 + a_radd) * 64
                                           + kb0 + a_cadd);
                ldm_x4(ah[mt][0], ah[mt][1], ah[mt][2], ah[mt][3],
                       stg + 0 * BUF_B + sw64(roff));
            }
#pragma unroll
            for (int bp = 0; bp < 2; bp++) {
                uint32_t roff = (uint32_t)((warp_n * 32 + bp * 16 + b_radd) * 64
                                           + kb0 + b_cadd);
                uint32_t h[4];
                ldm_x4(h[0], h[1], h[2], h[3], stg + 1 * BUF_B + sw64(roff));
#pragma unroll
                for (int mt = 0; mt < 4; mt++) {
                    mma_f16(acc[mt][2 * bp + 0], ah[mt], &h[0]);
                    mma_f16(acc[mt][2 * bp + 1], ah[mt], &h[2]);
                }
            }
        }
        stage++; if (stage >= G_NSTAGE) stage = 0;
    }

    const int qr = lane >> 2;
    const int qc = (lane & 3) * 2;
#pragma unroll
    for (int mt = 0; mt < 4; mt++) {
        int row = row_a0 + warp_m * 64 + mt * 16 + qr;
#pragma unroll
        for (int nt = 0; nt < 4; nt++) {
            int col = row_b0 + warp_n * 32 + nt * 8 + qc;
            if (Ch == nullptr) {
                *(float2*)(C + (size_t)row * N + col) =
                    make_float2(acc[mt][nt][0], acc[mt][nt][1]);
                *(float2*)(C + (size_t)(row + 8) * N + col) =
                    make_float2(acc[mt][nt][2], acc[mt][nt][3]);
            } else {
                *(uint32_t*)(Ch + (size_t)row * N + col) =
                    pack_h2(acc[mt][nt][0], acc[mt][nt][1]);
                *(uint32_t*)(Ch + (size_t)(row + 8) * N + col) =
                    pack_h2(acc[mt][nt][2], acc[mt][nt][3]);
            }
        }
    }
}

// ---------------------------------------------------------------------------
// HMMA fp16 flash attention (causal), plain fp16 Q/K/V/P.
// 128 q-rows/CTA, 64-kv tiles, 8 warps x 16 rows.
// 3-stage KV ring with depth-2 prefetch (wait<1> keeps next tile in flight).
// Smem: Q 16KB + 3 stages x {K 8KB, V 8KB} = 64KB. 2 CTAs/SM.
// ---------------------------------------------------------------------------
#define SM_Q 0
#define SM_KV0 16384
#define AT_STAGE_B 16384
#define AT_NSTAGE 3
#define AT_SMEM (SM_KV0 + AT_NSTAGE * AT_STAGE_B)   // 65536

__device__ __forceinline__ void at_issue_kv(
    const __half* __restrict__ qkvh,
    size_t qoff, size_t rs, int kv0, uint32_t sb, int stage, int tid)
{
    uint32_t base = sb + SM_KV0 + stage * AT_STAGE_B;
#pragma unroll
    for (int t = 0; t < 2; t++) {
        int idx = tid + t * 256;
        int r = idx >> 3;
        int ch = idx & 7;
        uint32_t so = sw128((uint32_t)(r * 128 + ch * 16));
        size_t gk = qoff + D_ + (size_t)(kv0 + r) * rs + ch * 8;
        size_t gv = qoff + 2 * D_ + (size_t)(kv0 + r) * rs + ch * 8;
        cp_async16(base + 0 * 8192 + so, qkvh + gk);
        cp_async16(base + 1 * 8192 + so, qkvh + gv);
    }
}

__global__ __launch_bounds__(256, 2) void attn_mma_kernel(
    const __half* __restrict__ qkvh, __half* __restrict__ yh)
{
    extern __shared__ char smc[];
    uint32_t sb = smem_u32(smc);
    const int tid = threadIdx.x;
    const int wid = tid >> 5;
    const int lane = tid & 31;
    const int b = blockIdx.z;
    const int h = blockIdx.y;
    const int qt = gridDim.x - 1 - blockIdx.x;   // long CTAs first
    const int q0 = qt * 128;
    const int wm = wid * 16;
    const int nkv = 2 * qt + 2;

    const size_t rs = 3 * D_;
    const size_t qoff = (size_t)(b * L_) * rs + h * HD_;

    // Prologue: group0 = Q + KV0; group1 = KV1 (nkv >= 2 always)
#pragma unroll
    for (int t = 0; t < 4; t++) {
        int idx = tid + t * 256;
        int r = idx >> 3;
        int ch = idx & 7;
        uint32_t so = sw128((uint32_t)(r * 128 + ch * 16));
        size_t g = qoff + (size_t)(q0 + r) * rs + ch * 8;
        cp_async16(sb + SM_Q + so, qkvh + g);
    }
    at_issue_kv(qkvh, qoff, rs, 0, sb, 0, tid);
    cp_commit();
    at_issue_kv(qkvh, qoff, rs, 64, sb, 1, tid);
    cp_commit();

    // ldmatrix lane address components
    const int lr = lane & 7;
    const int mat = lane >> 3;
    const int a_radd = lr + (mat & 1) * 8;       // A (non-trans)
    const int a_cadd = (mat >> 1) * 16;
    const int b_radd = lr + (mat >> 1) * 8;      // B (non-trans, K)
    const int b_cadd = (mat & 1) * 16;
    const int v_radd = lr + (mat & 1) * 8;       // B (trans, V)
    const int v_cadd = (mat >> 1) * 16;
    const int qr = lane >> 2;
    const int qc2 = (lane & 3) * 2;

    float m2[2] = {-1e30f, -1e30f};
    float l2[2] = {0.0f, 0.0f};
    float o[8][4];
#pragma unroll
    for (int ng = 0; ng < 8; ng++)
#pragma unroll
        for (int e = 0; e < 4; e++) o[ng][e] = 0.0f;

    int stage = 0;
    for (int jt = 0; jt < nkv; jt++) {
        if (jt < nkv - 1) cp_wait<1>();   // group jt done; jt+1 stays in flight
        else cp_wait<0>();
        __syncthreads();                  // all warps done with stage being reissued
        if (jt + 2 < nkv) {
            int ws = stage + 2; if (ws >= AT_NSTAGE) ws -= AT_NSTAGE;
            at_issue_kv(qkvh, qoff, rs, (jt + 2) * 64, sb, ws, tid);
            cp_commit();
        }

        const uint32_t kb = sb + SM_KV0 + stage * AT_STAGE_B;

        // ---- S = Q @ K^T ----
        float s[8][4];
#pragma unroll
        for (int ng = 0; ng < 8; ng++)
#pragma unroll
            for (int e = 0; e < 4; e++) s[ng][e] = 0.0f;

#pragma unroll
        for (int k = 0; k < 4; k++) {
            uint32_t ah[4];
            uint32_t aoff = sw128((uint32_t)((wm + a_radd) * 128 + k * 32 + a_cadd));
            ldm_x4(ah[0], ah[1], ah[2], ah[3], sb + SM_Q + aoff);
#pragma unroll
            for (int bp = 0; bp < 4; bp++) {
                uint32_t roff = sw128((uint32_t)((bp * 16 + b_radd) * 128
                                                 + k * 32 + b_cadd));
                uint32_t bh[4];
                ldm_x4(bh[0], bh[1], bh[2], bh[3], kb + 0 * 8192 + roff);
                mma_f16(s[2 * bp + 0], ah, &bh[0]);
                mma_f16(s[2 * bp + 1], ah, &bh[2]);
            }
        }

        // ---- scale + causal mask ----
        const float scale = 0.125f;
        if (jt >= nkv - 2) {
#pragma unroll
            for (int ng = 0; ng < 8; ng++)
#pragma unroll
                for (int e = 0; e < 4; e++) {
                    int rg = q0 + wm + qr + (e >> 1) * 8;
                    int cg = jt * 64 + ng * 8 + qc2 + (e & 1);
                    s[ng][e] = (cg > rg) ? -1e30f : s[ng][e] * scale;
                }
        } else {
#pragma unroll
            for (int ng = 0; ng < 8; ng++)
#pragma unroll
                for (int e = 0; e < 4; e++) s[ng][e] *= scale;
        }

        // ---- online softmax (per-warp; rows qr and qr+8) ----
#pragma unroll
        for (int t = 0; t < 2; t++) {
            float mx = -1e30f;
#pragma unroll
            for (int ng = 0; ng < 8; ng++)
                mx = fmaxf(mx, fmaxf(s[ng][2 * t], s[ng][2 * t + 1]));
            mx = fmaxf(mx, __shfl_xor_sync(0xffffffffu, mx, 1));
            mx = fmaxf(mx, __shfl_xor_sync(0xffffffffu, mx, 2));
            float mnew = fmaxf(m2[t], mx);
            float alpha = __expf(m2[t] - mnew);
            m2[t] = mnew;
            float sum = 0.0f;
#pragma unroll
            for (int ng = 0; ng < 8; ng++) {
                s[ng][2 * t] = __expf(s[ng][2 * t] - mnew);
                s[ng][2 * t + 1] = __expf(s[ng][2 * t + 1] - mnew);
                sum += s[ng][2 * t] + s[ng][2 * t + 1];
            }
            sum += __shfl_xor_sync(0xffffffffu, sum, 1);
            sum += __shfl_xor_sync(0xffffffffu, sum, 2);
            l2[t] = l2[t] * alpha + sum;
#pragma unroll
            for (int ng = 0; ng < 8; ng++) {
                o[ng][2 * t] *= alpha;
                o[ng][2 * t + 1] *= alpha;
            }
        }

        // ---- O += P @ V ----
#pragma unroll
        for (int kk = 0; kk < 4; kk++) {
            uint32_t pah[4];
            pah[0] = pack_h2(s[2 * kk][0], s[2 * kk][1]);
            pah[1] = pack_h2(s[2 * kk][2], s[2 * kk][3]);
            pah[2] = pack_h2(s[2 * kk + 1][0], s[2 * kk + 1][1]);
            pah[3] = pack_h2(s[2 * kk + 1][2], s[2 * kk + 1][3]);
#pragma unroll
            for (int gp = 0; gp < 4; gp++) {
                uint32_t roff = sw128((uint32_t)((kk * 16 + v_radd) * 128
                                                 + gp * 32 + v_cadd));
                uint32_t vh[4];
                ldm_x4_t(vh[0], vh[1], vh[2], vh[3], kb + 1 * 8192 + roff);
                mma_f16(o[2 * gp + 0], pah, &vh[0]);
                mma_f16(o[2 * gp + 1], pah, &vh[2]);
            }
        }
        stage++; if (stage >= AT_NSTAGE) stage = 0;
    }

    // ---- normalize + store y as plain fp16 ----
    float inv0 = 1.0f / l2[0];
    float inv1 = 1.0f / l2[1];
    int row0 = b * L_ + q0 + wm + qr;
#pragma unroll
    for (int ng = 0; ng < 8; ng++) {
        int col = h * HD_ + ng * 8 + qc2;
        *(uint32_t*)(yh + (size_t)row0 * D_ + col) =
            pack_h2(o[ng][0] * inv0, o[ng][1] * inv0);
        *(uint32_t*)(yh + (size_t)(row0 + 8) * D_ + col) =
            pack_h2(o[ng][2] * inv1, o[ng][3] * inv1);
    }
}

// ---------------------------------------------------------------------------
// kernel_launch
// ---------------------------------------------------------------------------
extern "C" void kernel_launch(void* const* d_in, const int* in_sizes, int n_in,
                              void* d_out, int out_size)
{
    const float* x     = (const float*)d_in[0];
    const float* Wqkv  = (const float*)d_in[1];
    const float* Wproj = (const float*)d_in[2];
    float* out = (float*)d_out;

    __half *qkvh, *xh, *yh, *wqh, *wph;
    cudaGetSymbolAddress((void**)&qkvh, g_qkv_h);
    cudaGetSymbolAddress((void**)&xh,  g_x_h);
    cudaGetSymbolAddress((void**)&yh,  g_y_h);
    cudaGetSymbolAddress((void**)&wqh, g_wqkv_h);
    cudaGetSymbolAddress((void**)&wph, g_wproj_h);

    cudaFuncSetAttribute(gemm_mma_kernel,
                         cudaFuncAttributeMaxDynamicSharedMemorySize, GEMM_SMEM);
    cudaFuncSetAttribute(attn_mma_kernel,
                         cudaFuncAttributeMaxDynamicSharedMemorySize, AT_SMEM);

    // 1) convert x to fp16 / transpose+convert weights to fp16
    {
        int n4 = NTOK * D_ / 4;
        convert_kernel<<<(n4 + 255) / 256, 256>>>(x, xh, n4);
    }
    transpose_convert_kernel<<<dim3(3 * D_ / 32, D_ / 32), dim3(32, 8)>>>(
        Wqkv, wqh, D_, 3 * D_);
    transpose_convert_kernel<<<dim3(D_ / 32, D_ / 32), dim3(32, 8)>>>(
        Wproj, wph, D_, D_);

    // 2) qkv (plain fp16) = x @ Wqkv
    gemm_mma_kernel<<<dim3(3 * D_ / 128, NTOK / 128), 256, GEMM_SMEM>>>(
        xh, wqh, nullptr, qkvh, NTOK, 3 * D_, D_);

    // 3) flash attention -> y (plain fp16)
    attn_mma_kernel<<<dim3(L_ / 128, H_, B_), 256, AT_SMEM>>>(qkvh, yh);

    // 4) out = y @ Wproj (fp32 output)
    gemm_mma_kernel<<<dim3(D_ / 128, NTOK / 128), 256, GEMM_SMEM>>>(
        yh, wph, out, nullptr, NTOK, D_, D_);
}